// round 9
// baseline (speedup 1.0000x reference)
#include <cuda_runtime.h>
#include <cuda_fp16.h>
#include <cstdint>
#include <cstddef>

#define T_SEQ 512
#define BATCH 128
#define DIN   1024
#define DOUT  1024
#define N4    4096          // 4 gates * DOUT, gate-interleaved: n = unit*4 + gate
#define GRID_LSTM 128

// ---------------- static device scratch (no allocations allowed) ----------------
__device__ __align__(256) __half g_WxH [(size_t)N4 * DIN];           // packed fp16 x-weights
__device__ __align__(256) __half g_WhH [(size_t)N4 * DOUT];          // packed fp16 h-weights
__device__ __align__(256) float  g_bias[N4];
__device__ __align__(256) __half g_XhH [(size_t)T_SEQ * BATCH * DIN];// fp16 tokens
__device__ __align__(256) __half g_hH  [2][BATCH * DOUT];            // ping-pong hidden state fp16
__device__ unsigned g_bar2[2][32];                                   // per-mt-group barrier counters

// ---------------- helpers ----------------
__device__ __forceinline__ void cp16(void* smem_dst, const void* gsrc) {
    unsigned s = (unsigned)__cvta_generic_to_shared(smem_dst);
    asm volatile("cp.async.cg.shared.global [%0], [%1], 16;\n" :: "r"(s), "l"(gsrc));
}

__device__ __forceinline__ void ldsm4(unsigned& r0, unsigned& r1, unsigned& r2, unsigned& r3,
                                      uint32_t addr) {
    asm volatile("ldmatrix.sync.aligned.m8n8.x4.shared.b16 {%0,%1,%2,%3}, [%4];"
                 : "=r"(r0), "=r"(r1), "=r"(r2), "=r"(r3) : "r"(addr));
}

__device__ __forceinline__ void mma16(float* d, const unsigned* a, const unsigned* b) {
    asm volatile(
        "mma.sync.aligned.m16n8k16.row.col.f32.f16.f16.f32 "
        "{%0,%1,%2,%3}, {%4,%5,%6,%7}, {%8,%9}, {%0,%1,%2,%3};\n"
        : "+f"(d[0]), "+f"(d[1]), "+f"(d[2]), "+f"(d[3])
        : "r"(a[0]), "r"(a[1]), "r"(a[2]), "r"(a[3]), "r"(b[0]), "r"(b[1]));
}

__device__ __forceinline__ float sigm(float x) { return 1.f / (1.f + __expf(-x)); }

__device__ __forceinline__ uint32_t smem_u32(const void* p) {
    return (uint32_t)__cvta_generic_to_shared(p);
}

// ---------------- kernel 1: pack weights / convert tokens / reset state ----------------
__global__ void __launch_bounds__(256) pack_kernel(
    const float* __restrict__ tokens,
    const float* __restrict__ Wf, const float* __restrict__ bf,
    const float* __restrict__ Wi, const float* __restrict__ bi,
    const float* __restrict__ Wc, const float* __restrict__ bc,
    const float* __restrict__ Wo, const float* __restrict__ bo)
{
    size_t tid = (size_t)blockIdx.x * blockDim.x + threadIdx.x;
    size_t nth = (size_t)gridDim.x * blockDim.x;
    if (tid < 64) g_bar2[tid >> 5][tid & 31] = 0;   // reset barriers every launch (graph replays)

    for (size_t i = tid; i < (size_t)N4 * 1024; i += nth) {
        int n = (int)(i >> 10), k = (int)(i & 1023);
        int u = n >> 2, g = n & 3;
        const float* W = (g == 0) ? Wf : (g == 1) ? Wi : (g == 2) ? Wc : Wo;
        g_WxH[i] = __float2half_rn(W[(size_t)u * 2048 + k]);
        g_WhH[i] = __float2half_rn(W[(size_t)u * 2048 + 1024 + k]);
    }
    for (size_t i = tid; i < (size_t)N4; i += nth) {
        int u = (int)(i >> 2), g = (int)(i & 3);
        const float* bb = (g == 0) ? bf : (g == 1) ? bi : (g == 2) ? bc : bo;
        g_bias[i] = bb[u];
    }
    for (size_t i = tid; i < (size_t)T_SEQ * BATCH * DIN; i += nth)
        g_XhH[i] = __float2half_rn(tokens[i]);
    for (size_t i = tid; i < (size_t)BATCH * DOUT; i += nth)
        g_hH[0][i] = __float2half_rn(0.f);   // h0 = 0
}

// ---------------- kernel 2: fused persistent LSTM ----------------
// 128 CTAs (2 independent mt groups x 64 nt), 64x64 tile, 8 warps 2(M)x4(N), warp 32x16.
// Wh slice (64x1024 fp16) resident in smem. Per step: h-GEMM (K=1024, 4 chunks of 256)
// then, in the barrier shadow, x-GEMM for step t+1 into registers (accx), K=1024 in
// 8 chunks of 128 (X and Wx streamed through the same staging buffers).
#define LS_BSAS 1032                            // halfs per resident-B row (1024 + 8 pad)
#define LS_BT   (64 * LS_BSAS)                  // 66048 halfs
#define ST_SAS  136                             // halfs per staging row (128 + 8 pad)
#define ST_BUF  (64 * ST_SAS)                   // 8704 halfs per buffer
#define LS_SMEM ((LS_BT + 4 * ST_BUF) * 2)      // 201728 bytes

__global__ void __launch_bounds__(256) lstm_fused(float* __restrict__ out) {
    extern __shared__ __half smL[];
    __half* sB = smL;                 // resident Wh slice
    __half* sS = smL + LS_BT;         // 4 staging buffers (64 x 128 halfs each)

    const int tid = threadIdx.x, lane = tid & 31, wid = tid >> 5;
    const int wm = wid >> 2, wn = wid & 3;
    const int gid = lane >> 2, tig = lane & 3;
    const int bx = blockIdx.x;
    const int mt = bx >> 6, nt = bx & 63;
    const int m0 = mt * 64, n0 = nt * 64;

    const uint32_t sBb = smem_u32(sB);
    const uint32_t sSb = smem_u32(sS);
    volatile unsigned* barp = (volatile unsigned*)&g_bar2[mt][0];

    const int aR = (lane & 15), aK = ((lane >> 4) << 3);
    const int bR = (lane & 7) + ((lane >> 4) << 3), bK = ((lane >> 3) & 1) << 3;

    // bias registers (per-thread cols)
    float bs0[2], bs1[2];
    #pragma unroll
    for (int ni = 0; ni < 2; ni++) {
        int col = n0 + wn * 16 + ni * 8 + 2 * tig;
        bs0[ni] = g_bias[col];
        bs1[ni] = g_bias[col + 1];
    }

    // preload resident Wh slice: 64 rows x 1024 halfs
    {
        const __half* Wb = g_WhH + (size_t)n0 * 1024;
        #pragma unroll 4
        for (int i = 0; i < 32; i++) {
            int idx = tid + i * 256;
            int r = idx >> 7, s = idx & 127;
            cp16(sB + r * LS_BSAS + s * 8, Wb + (size_t)r * 1024 + s * 8);
        }
        asm volatile("cp.async.commit_group;\n");
        asm volatile("cp.async.wait_group 0;\n");
        __syncthreads();
    }

    float cst[2][2][2] = {};     // c-state (even-tig lanes)
    float accx[2][2][4];         // x-part preactivation for the upcoming step

    // ---- x-GEMM chunk loader: 64 rows x 128 halfs each for X and Wx ----
    // 1024 cp16 per tile = 16 per row: r_ = ix_>>4, s_ = ix_&15  (FIXED)
    #define LOADX(c, tX) do {                                                       \
        int cb_ = (c) & 1;                                                          \
        __half* dX_ = sS + cb_ * ST_BUF;                                            \
        __half* dW_ = sS + (2 + cb_) * ST_BUF;                                      \
        const __half* sx_ = g_XhH + ((size_t)(tX) * BATCH + m0) * 1024 + (c) * 128; \
        const __half* sw_ = g_WxH + (size_t)n0 * 1024 + (c) * 128;                  \
        _Pragma("unroll")                                                           \
        for (int i_ = 0; i_ < 4; i_++) { int ix_ = tid + i_ * 256;                  \
            int r_ = ix_ >> 4, s_ = ix_ & 15;                                       \
            cp16(dX_ + r_ * ST_SAS + s_ * 8, sx_ + (size_t)r_ * 1024 + s_ * 8); }   \
        _Pragma("unroll")                                                           \
        for (int i_ = 0; i_ < 4; i_++) { int ix_ = tid + i_ * 256;                  \
            int r_ = ix_ >> 4, s_ = ix_ & 15;                                       \
            cp16(dW_ + r_ * ST_SAS + s_ * 8, sw_ + (size_t)r_ * 1024 + s_ * 8); }   \
        asm volatile("cp.async.commit_group;\n");                                   \
    } while (0)

    #define XPHASE(tX) do {                                                         \
        _Pragma("unroll")                                                           \
        for (int mi = 0; mi < 2; mi++)                                              \
            _Pragma("unroll")                                                       \
            for (int ni = 0; ni < 2; ni++) {                                        \
                accx[mi][ni][0] = bs0[ni]; accx[mi][ni][1] = bs1[ni];               \
                accx[mi][ni][2] = bs0[ni]; accx[mi][ni][3] = bs1[ni];               \
            }                                                                       \
        LOADX(0, tX);                                                               \
        _Pragma("unroll 1")                                                         \
        for (int c = 0; c < 8; c++) {                                               \
            asm volatile("cp.async.wait_group 0;\n");                               \
            __syncthreads();                                                        \
            if (c + 1 < 8) LOADX(c + 1, tX);                                        \
            uint32_t xb_ = sSb + (uint32_t)((c & 1) * ST_BUF) * 2;                  \
            uint32_t wb_ = sSb + (uint32_t)((2 + (c & 1)) * ST_BUF) * 2;            \
            _Pragma("unroll")                                                       \
            for (int kk = 0; kk < 8; kk++) {                                        \
                unsigned bfr[2][2];                                                 \
                ldsm4(bfr[0][0], bfr[0][1], bfr[1][0], bfr[1][1],                   \
                      wb_ + (uint32_t)((wn * 16 + bR) * ST_SAS + kk * 16 + bK) * 2);\
                unsigned af[2][4];                                                  \
                _Pragma("unroll")                                                   \
                for (int mi = 0; mi < 2; mi++)                                      \
                    ldsm4(af[mi][0], af[mi][1], af[mi][2], af[mi][3],               \
                          xb_ + (uint32_t)((wm * 32 + mi * 16 + aR) * ST_SAS + kk * 16 + aK) * 2); \
                _Pragma("unroll")                                                   \
                for (int mi = 0; mi < 2; mi++)                                      \
                    _Pragma("unroll")                                               \
                    for (int ni = 0; ni < 2; ni++)                                  \
                        mma16(accx[mi][ni], af[mi], bfr[ni]);                       \
            }                                                                       \
        }                                                                           \
    } while (0)

    // ---- h-GEMM chunk loader: K=256 chunk across a buffer pair ----
    // 2048 cp16 = 32 per row: r_ = ix_>>5, s_ = ix_&31
    #define LOADH(c, hin_) do {                                                     \
        int pr_ = (c) & 1;                                                          \
        __half* d_ = sS + pr_ * 2 * ST_BUF;                                         \
        const __half* sh_ = (hin_) + (size_t)m0 * 1024 + (c) * 256;                 \
        _Pragma("unroll")                                                           \
        for (int i_ = 0; i_ < 8; i_++) { int ix_ = tid + i_ * 256;                  \
            int r_ = ix_ >> 5, s_ = ix_ & 31;                                       \
            cp16(d_ + (s_ >> 4) * ST_BUF + r_ * ST_SAS + (s_ & 15) * 8,             \
                 sh_ + (size_t)r_ * 1024 + s_ * 8); }                               \
        asm volatile("cp.async.commit_group;\n");                                   \
    } while (0)

    // prologue: x-part for step 0
    XPHASE(0);

    for (int t = 0; t < T_SEQ; t++) {
        const __half* hin = g_hH[t & 1];
        __half*      hout = g_hH[(t + 1) & 1];

        float acch[2][2][4] = {};

        LOADH(0, hin);
        #pragma unroll 1
        for (int c = 0; c < 4; c++) {
            asm volatile("cp.async.wait_group 0;\n");
            __syncthreads();
            if (c + 1 < 4) LOADH(c + 1, hin);
            uint32_t ab = sSb + (uint32_t)((c & 1) * 2 * ST_BUF) * 2;
            #pragma unroll
            for (int kk = 0; kk < 16; kk++) {
                unsigned bfr[2][2];
                ldsm4(bfr[0][0], bfr[0][1], bfr[1][0], bfr[1][1],
                      sBb + (uint32_t)((wn * 16 + bR) * LS_BSAS + c * 256 + kk * 16 + bK) * 2);
                unsigned af[2][4];
                #pragma unroll
                for (int mi = 0; mi < 2; mi++)
                    ldsm4(af[mi][0], af[mi][1], af[mi][2], af[mi][3],
                          ab + (uint32_t)((kk >> 3) * ST_BUF +
                               (wm * 32 + mi * 16 + aR) * ST_SAS + (kk & 7) * 16 + aK) * 2);
                #pragma unroll
                for (int mi = 0; mi < 2; mi++)
                    #pragma unroll
                    for (int ni = 0; ni < 2; ni++)
                        mma16(acch[mi][ni], af[mi], bfr[ni]);
            }
        }

        // elementwise LSTM cell: preact = acch + accx (bias already inside accx)
        #pragma unroll
        for (int mi = 0; mi < 2; mi++)
            #pragma unroll
            for (int ni = 0; ni < 2; ni++) {
                int row = m0 + wm * 32 + mi * 16 + gid;
                int col = n0 + wn * 16 + ni * 8 + 2 * tig;
                float v0 = acch[mi][ni][0] + accx[mi][ni][0];
                float v1 = acch[mi][ni][1] + accx[mi][ni][1];
                float v2 = acch[mi][ni][2] + accx[mi][ni][2];
                float v3 = acch[mi][ni][3] + accx[mi][ni][3];
                float p0 = __shfl_xor_sync(0xffffffffu, v0, 1);
                float p1 = __shfl_xor_sync(0xffffffffu, v1, 1);
                float p2 = __shfl_xor_sync(0xffffffffu, v2, 1);
                float p3 = __shfl_xor_sync(0xffffffffu, v3, 1);
                if (!(tig & 1)) {
                    int u = col >> 2;
                    {
                        float f = sigm(v0), ii = sigm(v1), gg = tanhf(p0), oo = sigm(p1);
                        float cn = cst[mi][ni][0] * f + ii * gg;
                        cst[mi][ni][0] = cn;
                        float h = oo * tanhf(cn);
                        out[(size_t)t * (BATCH * DOUT) + (size_t)row * DOUT + u] = h;
                        hout[row * DOUT + u] = __float2half_rn(h);
                    }
                    {
                        float f = sigm(v2), ii = sigm(v3), gg = tanhf(p2), oo = sigm(p3);
                        float cn = cst[mi][ni][1] * f + ii * gg;
                        cst[mi][ni][1] = cn;
                        float h = oo * tanhf(cn);
                        out[(size_t)t * (BATCH * DOUT) + (size_t)(row + 8) * DOUT + u] = h;
                        hout[(row + 8) * DOUT + u] = __float2half_rn(h);
                    }
                }
            }

        __syncthreads();
        if (t == T_SEQ - 1) break;   // no successor step; skip x-phase and barrier

        // arrive, then hide the next step's x-GEMM inside the barrier shadow
        if (tid == 0) {
            __threadfence();
            atomicAdd((unsigned*)barp, 1u);
        }

        XPHASE(t + 1);

        if (tid == 0) {
            unsigned tgt = (unsigned)(t + 1) * (GRID_LSTM / 2);
            while (*barp < tgt) { }
            __threadfence();
        }
        __syncthreads();
    }
}

// ---------------- launch ----------------
extern "C" void kernel_launch(void* const* d_in, const int* in_sizes, int n_in,
                              void* d_out, int out_size) {
    const float* tokens = (const float*)d_in[0];
    const float* Wf = (const float*)d_in[1]; const float* bf = (const float*)d_in[2];
    const float* Wi = (const float*)d_in[3]; const float* bi = (const float*)d_in[4];
    const float* Wc = (const float*)d_in[5]; const float* bc = (const float*)d_in[6];
    const float* Wo = (const float*)d_in[7]; const float* bo = (const float*)d_in[8];

    cudaFuncSetAttribute(lstm_fused, cudaFuncAttributeMaxDynamicSharedMemorySize, LS_SMEM);

    pack_kernel<<<2048, 256>>>(tokens, Wf, bf, Wi, bi, Wc, bc, Wo, bo);
    lstm_fused<<<GRID_LSTM, 256, LS_SMEM>>>((float*)d_out);
}

// round 10
// speedup vs baseline: 1.2708x; 1.2708x over previous
#include <cuda_runtime.h>
#include <cuda_fp16.h>
#include <cstdint>
#include <cstddef>

#define T_SEQ 512
#define BATCH 128
#define DIN   1024
#define DOUT  1024
#define N4    4096          // 4 gates * DOUT, gate-interleaved: n = unit*4 + gate
#define GRID_LSTM 128

// ---------------- static device scratch (no allocations allowed) ----------------
__device__ __align__(256) float  g_Z   [(size_t)T_SEQ * BATCH * N4]; // 1 GiB preactivations (+bias)
__device__ __align__(256) __half g_WxH [(size_t)N4 * DIN];           // packed fp16 x-weights
__device__ __align__(256) __half g_WhH [(size_t)N4 * DOUT];          // packed fp16 h-weights
__device__ __align__(256) float  g_bias[N4];
__device__ __align__(256) __half g_XhH [(size_t)T_SEQ * BATCH * DIN];// fp16 tokens
__device__ __align__(256) __half g_hH  [2][BATCH * DOUT];            // ping-pong hidden state fp16
__device__ unsigned g_bar2[2][32];                                   // per-mt-group barrier counters

// ---------------- helpers ----------------
__device__ __forceinline__ void cp16(void* smem_dst, const void* gsrc) {
    unsigned s = (unsigned)__cvta_generic_to_shared(smem_dst);
    asm volatile("cp.async.cg.shared.global [%0], [%1], 16;\n" :: "r"(s), "l"(gsrc));
}

__device__ __forceinline__ void ldsm4(unsigned& r0, unsigned& r1, unsigned& r2, unsigned& r3,
                                      uint32_t addr) {
    asm volatile("ldmatrix.sync.aligned.m8n8.x4.shared.b16 {%0,%1,%2,%3}, [%4];"
                 : "=r"(r0), "=r"(r1), "=r"(r2), "=r"(r3) : "r"(addr));
}

__device__ __forceinline__ void mma16(float* d, const unsigned* a, const unsigned* b) {
    asm volatile(
        "mma.sync.aligned.m16n8k16.row.col.f32.f16.f16.f32 "
        "{%0,%1,%2,%3}, {%4,%5,%6,%7}, {%8,%9}, {%0,%1,%2,%3};\n"
        : "+f"(d[0]), "+f"(d[1]), "+f"(d[2]), "+f"(d[3])
        : "r"(a[0]), "r"(a[1]), "r"(a[2]), "r"(a[3]), "r"(b[0]), "r"(b[1]));
}

__device__ __forceinline__ float sigm(float x) { return 1.f / (1.f + __expf(-x)); }

__device__ __forceinline__ uint32_t smem_u32(const void* p) {
    return (uint32_t)__cvta_generic_to_shared(p);
}

// ---------------- kernel 1: pack weights / convert tokens / reset state ----------------
__global__ void __launch_bounds__(256) pack_kernel(
    const float* __restrict__ tokens,
    const float* __restrict__ Wf, const float* __restrict__ bf,
    const float* __restrict__ Wi, const float* __restrict__ bi,
    const float* __restrict__ Wc, const float* __restrict__ bc,
    const float* __restrict__ Wo, const float* __restrict__ bo)
{
    size_t tid = (size_t)blockIdx.x * blockDim.x + threadIdx.x;
    size_t nth = (size_t)gridDim.x * blockDim.x;
    if (tid < 64) g_bar2[tid >> 5][tid & 31] = 0;   // reset barriers every launch (graph replays)

    for (size_t i = tid; i < (size_t)N4 * 1024; i += nth) {
        int n = (int)(i >> 10), k = (int)(i & 1023);
        int u = n >> 2, g = n & 3;
        const float* W = (g == 0) ? Wf : (g == 1) ? Wi : (g == 2) ? Wc : Wo;
        g_WxH[i] = __float2half_rn(W[(size_t)u * 2048 + k]);
        g_WhH[i] = __float2half_rn(W[(size_t)u * 2048 + 1024 + k]);
    }
    for (size_t i = tid; i < (size_t)N4; i += nth) {
        int u = (int)(i >> 2), g = (int)(i & 3);
        const float* bb = (g == 0) ? bf : (g == 1) ? bi : (g == 2) ? bc : bo;
        g_bias[i] = bb[u];
    }
    for (size_t i = tid; i < (size_t)T_SEQ * BATCH * DIN; i += nth)
        g_XhH[i] = __float2half_rn(tokens[i]);
    for (size_t i = tid; i < (size_t)BATCH * DOUT; i += nth)
        g_hH[0][i] = __float2half_rn(0.f);   // h0 = 0
}

// ---------------- kernel 2: fp16 mma: Z = X @ Wx^T + b ----------------
// CTA tile 128x128, 256 threads = 8 warps 2(M)x4(N); warp tile 64x32; K-chunk 64.
// 2 CTAs/SM -> 16 warps/SM for latency hiding.
#define PC_SAS  72                    // halfs per smem row (64 data + 8 pad)
#define PC_PT   (128 * PC_SAS)        // halfs per 128x64 tile (9216)
#define PC_SMEM (2 * 2 * PC_PT * 2)   // bytes = 73728 (A,B x double buffer)

__global__ void __launch_bounds__(256, 2) precompute_fp16() {
    extern __shared__ __half smH[];
    const int tid = threadIdx.x, lane = tid & 31, wid = tid >> 5;
    const int wm = wid >> 2, wn = wid & 3;
    const int gid = lane >> 2, tig = lane & 3;
    const int bx = blockIdx.x;
    const int mt = bx >> 5, nt = bx & 31;        // nt fastest: A tile shared in L2
    const size_t m0 = (size_t)mt * 128;
    const int n0 = nt * 128;

    const __half* Ax = g_XhH + m0 * 1024;
    const __half* Bw = g_WxH + (size_t)n0 * 1024;
    const uint32_t smb = smem_u32(smH);

    // ldmatrix per-thread address components
    const int aR = (lane & 15), aK = ((lane >> 4) << 3);
    const int bR = (lane & 7) + ((lane >> 4) << 3), bK = ((lane >> 3) & 1) << 3;

    float acc[4][4][4] = {};

    // chunk loader (A, B -> buffer): 128 rows x 64 halfs each; 1024 cp16/tile, 4/thread
    #define PC_LOAD(buf, c) do {                                                   \
        __half* d_ = smH + (buf) * 2 * PC_PT;                                      \
        int k0_ = (c) * 64;                                                        \
        _Pragma("unroll")                                                          \
        for (int i_ = 0; i_ < 4; i_++) { int ix_ = tid + i_ * 256;                 \
            int r_ = ix_ >> 3, s_ = ix_ & 7;                                       \
            cp16(d_ + r_ * PC_SAS + s_ * 8, Ax + (size_t)r_ * 1024 + k0_ + s_ * 8);} \
        _Pragma("unroll")                                                          \
        for (int i_ = 0; i_ < 4; i_++) { int ix_ = tid + i_ * 256;                 \
            int r_ = ix_ >> 3, s_ = ix_ & 7;                                       \
            cp16(d_ + PC_PT + r_ * PC_SAS + s_ * 8, Bw + (size_t)r_ * 1024 + k0_ + s_ * 8);} \
        asm volatile("cp.async.commit_group;\n");                                  \
    } while (0)

    PC_LOAD(0, 0);

    #pragma unroll 1
    for (int c = 0; c < 16; c++) {
        asm volatile("cp.async.wait_group 0;\n");
        __syncthreads();                          // chunk c resident; buf (c+1)&1 free
        if (c + 1 < 16) PC_LOAD((c + 1) & 1, c + 1);

        const uint32_t base = smb + (uint32_t)((c & 1) * 2 * PC_PT) * 2;
        #pragma unroll
        for (int kk = 0; kk < 4; kk++) {
            const int ko = kk * 16;
            unsigned bfr[4][2];
            #pragma unroll
            for (int nb = 0; nb < 2; nb++) {
                uint32_t ad = base + (uint32_t)PC_PT * 2 +
                              (uint32_t)((wn * 32 + nb * 16 + bR) * PC_SAS + ko + bK) * 2;
                ldsm4(bfr[2 * nb][0], bfr[2 * nb][1], bfr[2 * nb + 1][0], bfr[2 * nb + 1][1], ad);
            }
            unsigned af[4][4];
            #pragma unroll
            for (int mi = 0; mi < 4; mi++) {
                uint32_t ad = base + (uint32_t)((wm * 64 + mi * 16 + aR) * PC_SAS + ko + aK) * 2;
                ldsm4(af[mi][0], af[mi][1], af[mi][2], af[mi][3], ad);
            }
            #pragma unroll
            for (int mi = 0; mi < 4; mi++)
                #pragma unroll
                for (int ni = 0; ni < 4; ni++)
                    mma16(acc[mi][ni], af[mi], bfr[ni]);
        }
    }

    // epilogue: add bias, write Z
    #pragma unroll
    for (int mi = 0; mi < 4; mi++)
        #pragma unroll
        for (int ni = 0; ni < 4; ni++) {
            size_t row = m0 + wm * 64 + mi * 16 + gid;
            int col = n0 + wn * 32 + ni * 8 + 2 * tig;
            float b0 = g_bias[col], b1 = g_bias[col + 1];
            float2 v0 = make_float2(acc[mi][ni][0] + b0, acc[mi][ni][1] + b1);
            float2 v1 = make_float2(acc[mi][ni][2] + b0, acc[mi][ni][3] + b1);
            *reinterpret_cast<float2*>(&g_Z[row * N4 + col])       = v0;
            *reinterpret_cast<float2*>(&g_Z[(row + 8) * N4 + col]) = v1;
        }
}

// ---------------- kernel 3: persistent recurrent LSTM, 512 threads (16 warps) ----------
// 128 CTAs (2 independent mt groups x 64 nt), 64x64 tile, 16 warps 4(M)x4(N),
// warp tile 16x16 (2 ldsm : 4 mma). Wh slice resident in smem; A in 4 chunks of 256.
#define LS_BSAS 1032                            // halfs per resident-B row (1024 + 8 pad)
#define LS_BT   (64 * LS_BSAS)                  // 66048 halfs
#define ST_SAS  136                             // halfs per staging row (128 + 8 pad)
#define ST_BUF  (64 * ST_SAS)                   // 8704 halfs per sub-buffer
#define LS_SMEM ((LS_BT + 4 * ST_BUF) * 2)      // 201728 bytes

__global__ void __launch_bounds__(512) lstm_fp16(float* __restrict__ out) {
    extern __shared__ __half smL[];
    __half* sB = smL;                 // resident Wh slice
    __half* sA = smL + LS_BT;         // 4 staging sub-buffers (2 chunk pairs)

    const int tid = threadIdx.x, lane = tid & 31, wid = tid >> 5;
    const int wm = wid >> 2, wn = wid & 3;       // 4(M) x 4(N)
    const int gid = lane >> 2, tig = lane & 3;
    const int bx = blockIdx.x;
    const int mt = bx >> 6, nt = bx & 63;
    const int m0 = mt * 64, n0 = nt * 64;

    const uint32_t sBb = smem_u32(sB);
    const uint32_t sAb = smem_u32(sA);
    volatile unsigned* barp = (volatile unsigned*)&g_bar2[mt][0];

    const int aR = (lane & 15), aK = ((lane >> 4) << 3);
    const int bR = (lane & 7) + ((lane >> 4) << 3), bK = ((lane >> 3) & 1) << 3;

    // preload resident Wh slice: 64 rows x 1024 halfs = 8192 cp16, 16/thread
    {
        const __half* Wb = g_WhH + (size_t)n0 * 1024;
        #pragma unroll 4
        for (int i = 0; i < 16; i++) {
            int idx = tid + i * 512;
            int r = idx >> 7, s = idx & 127;
            cp16(sB + r * LS_BSAS + s * 8, Wb + (size_t)r * 1024 + s * 8);
        }
        asm volatile("cp.async.commit_group;\n");
        asm volatile("cp.async.wait_group 0;\n");
        __syncthreads();
    }

    float cst[2][2] = {};   // c-state (even-tig lanes): [ni][row/row+8]

    // ---- A chunk loader: 64 rows x 256 halfs = 2048 cp16, 4/thread ----
    #define LOADH(c, hin_) do {                                                     \
        int pr_ = (c) & 1;                                                          \
        __half* d_ = sA + pr_ * 2 * ST_BUF;                                         \
        const __half* sh_ = (hin_) + (size_t)m0 * 1024 + (c) * 256;                 \
        _Pragma("unroll")                                                           \
        for (int i_ = 0; i_ < 4; i_++) { int ix_ = tid + i_ * 512;                  \
            int r_ = ix_ >> 5, s_ = ix_ & 31;                                       \
            cp16(d_ + (s_ >> 4) * ST_BUF + r_ * ST_SAS + (s_ & 15) * 8,             \
                 sh_ + (size_t)r_ * 1024 + s_ * 8); }                               \
        asm volatile("cp.async.commit_group;\n");                                   \
    } while (0)

    for (int t = 0; t < T_SEQ; t++) {
        const __half* hin = g_hH[t & 1];
        __half*      hout = g_hH[(t + 1) & 1];
        const float* Zt   = g_Z + (size_t)t * BATCH * N4;

        // prefetch Z fragments (latency hides under the GEMM)
        float2 z[2][2];
        #pragma unroll
        for (int ni = 0; ni < 2; ni++) {
            int row = m0 + wm * 16 + gid;
            int col = n0 + wn * 16 + ni * 8 + 2 * tig;
            z[ni][0] = *reinterpret_cast<const float2*>(&Zt[(size_t)row * N4 + col]);
            z[ni][1] = *reinterpret_cast<const float2*>(&Zt[(size_t)(row + 8) * N4 + col]);
        }

        float acc[2][4] = {};

        LOADH(0, hin);
        #pragma unroll 1
        for (int c = 0; c < 4; c++) {
            asm volatile("cp.async.wait_group 0;\n");
            __syncthreads();
            if (c + 1 < 4) LOADH(c + 1, hin);
            uint32_t ab = sAb + (uint32_t)((c & 1) * 2 * ST_BUF) * 2;
            #pragma unroll
            for (int kk = 0; kk < 16; kk++) {
                unsigned bfr[2][2];
                ldsm4(bfr[0][0], bfr[0][1], bfr[1][0], bfr[1][1],
                      sBb + (uint32_t)((wn * 16 + bR) * LS_BSAS + c * 256 + kk * 16 + bK) * 2);
                unsigned af[4];
                ldsm4(af[0], af[1], af[2], af[3],
                      ab + (uint32_t)((kk >> 3) * ST_BUF +
                           (wm * 16 + aR) * ST_SAS + (kk & 7) * 16 + aK) * 2);
                #pragma unroll
                for (int ni = 0; ni < 2; ni++)
                    mma16(acc[ni], af, bfr[ni]);
            }
        }

        // elementwise LSTM cell (gate pairs in adjacent lanes; shfl_xor(1) completes quads)
        #pragma unroll
        for (int ni = 0; ni < 2; ni++) {
            int row = m0 + wm * 16 + gid;
            int col = n0 + wn * 16 + ni * 8 + 2 * tig;
            float v0 = acc[ni][0] + z[ni][0].x;
            float v1 = acc[ni][1] + z[ni][0].y;
            float v2 = acc[ni][2] + z[ni][1].x;
            float v3 = acc[ni][3] + z[ni][1].y;
            float p0 = __shfl_xor_sync(0xffffffffu, v0, 1);
            float p1 = __shfl_xor_sync(0xffffffffu, v1, 1);
            float p2 = __shfl_xor_sync(0xffffffffu, v2, 1);
            float p3 = __shfl_xor_sync(0xffffffffu, v3, 1);
            if (!(tig & 1)) {
                int u = col >> 2;
                {
                    float f = sigm(v0), ii = sigm(v1), gg = tanhf(p0), oo = sigm(p1);
                    float cn = cst[ni][0] * f + ii * gg;
                    cst[ni][0] = cn;
                    float h = oo * tanhf(cn);
                    out[(size_t)t * (BATCH * DOUT) + (size_t)row * DOUT + u] = h;
                    hout[row * DOUT + u] = __float2half_rn(h);
                }
                {
                    float f = sigm(v2), ii = sigm(v3), gg = tanhf(p2), oo = sigm(p3);
                    float cn = cst[ni][1] * f + ii * gg;
                    cst[ni][1] = cn;
                    float h = oo * tanhf(cn);
                    out[(size_t)t * (BATCH * DOUT) + (size_t)(row + 8) * DOUT + u] = h;
                    hout[(row + 8) * DOUT + u] = __float2half_rn(h);
                }
            }
        }

        // per-group barrier (64 CTAs): h(t) of this mt group visible before step t+1
        __syncthreads();
        if (tid == 0) {
            __threadfence();
            atomicAdd((unsigned*)barp, 1u);
            unsigned tgt = (unsigned)(t + 1) * (GRID_LSTM / 2);
            while (*barp < tgt) { }
            __threadfence();
        }
        __syncthreads();
    }
}

// ---------------- launch ----------------
extern "C" void kernel_launch(void* const* d_in, const int* in_sizes, int n_in,
                              void* d_out, int out_size) {
    const float* tokens = (const float*)d_in[0];
    const float* Wf = (const float*)d_in[1]; const float* bf = (const float*)d_in[2];
    const float* Wi = (const float*)d_in[3]; const float* bi = (const float*)d_in[4];
    const float* Wc = (const float*)d_in[5]; const float* bc = (const float*)d_in[6];
    const float* Wo = (const float*)d_in[7]; const float* bo = (const float*)d_in[8];

    cudaFuncSetAttribute(precompute_fp16, cudaFuncAttributeMaxDynamicSharedMemorySize, PC_SMEM);
    cudaFuncSetAttribute(lstm_fp16,       cudaFuncAttributeMaxDynamicSharedMemorySize, LS_SMEM);

    pack_kernel<<<2048, 256>>>(tokens, Wf, bf, Wi, bi, Wc, bc, Wo, bo);
    precompute_fp16<<<512 * 32, 256, PC_SMEM>>>();
    lstm_fp16<<<GRID_LSTM, 512, LS_SMEM>>>((float*)d_out);
}